// round 10
// baseline (speedup 1.0000x reference)
#include <cuda_runtime.h>
#include <cuda_fp16.h>
#include <cstdint>

#define E_ 8
#define T_ 16384
#define D_ 2048
#define H_ 1024

// ---------------- scratch: fp16 operands, plain row-major ---------------------
__device__ __align__(1024) __half g_x [T_ * (size_t)D_];
__device__ __align__(1024) __half g_w1[E_ * (size_t)H_ * D_];
__device__ __align__(1024) __half g_w3[E_ * (size_t)H_ * D_];
__device__ __align__(1024) __half g_w2[E_ * (size_t)D_ * H_];
__device__ __align__(1024) __half g_h [T_ * (size_t)H_];

// ---------------- coordination state (reset by init_cnt each call) ------------
__device__ int g_ticket;        // pack ticket queue head (2048 tickets)
__device__ int g_w2cnt;         // w2 pack done counter  (target 512)
__device__ int g_w13cnt[8];     // per-expert w1+w3 pack counters (target 64)
__device__ int g_xcnt[128];     // per-128-row x pack counters (target 8)
__device__ int g_hcnt[128];     // per-128-row h produce counters (target 16)

// ---------------- helpers ----------------
__device__ __forceinline__ uint32_t smem_u32(const void* p) {
    uint32_t a;
    asm("{ .reg .u64 t; cvta.to.shared.u64 t, %1; cvt.u32.u64 %0, t; }" : "=r"(a) : "l"(p));
    return a;
}
__device__ __forceinline__ uint32_t f22h(float lo, float hi) {   // fp16x2 {lo,hi}
    uint32_t r;
    asm("cvt.rn.f16x2.f32 %0, %1, %2;" : "=r"(r) : "f"(hi), "f"(lo));
    return r;
}
__device__ __forceinline__ void cp16(__half* sdst, const __half* gsrc) {
    uint32_t s = smem_u32(sdst);
    asm volatile("cp.async.cg.shared.global [%0], [%1], 16;" :: "r"(s), "l"(gsrc) : "memory");
}
__device__ __forceinline__ void ldm_x4(uint32_t& r0, uint32_t& r1, uint32_t& r2, uint32_t& r3,
                                       uint32_t addr) {
    asm volatile("ldmatrix.sync.aligned.m8n8.x4.shared.b16 {%0,%1,%2,%3}, [%4];"
                 : "=r"(r0), "=r"(r1), "=r"(r2), "=r"(r3) : "r"(addr));
}
__device__ __forceinline__ void mma_f16(float* c, const uint32_t* a, const uint32_t* b) {
    asm volatile(
        "mma.sync.aligned.m16n8k16.row.col.f32.f16.f16.f32 "
        "{%0,%1,%2,%3}, {%4,%5,%6,%7}, {%8,%9}, {%0,%1,%2,%3};"
        : "+f"(c[0]), "+f"(c[1]), "+f"(c[2]), "+f"(c[3])
        : "r"(a[0]), "r"(a[1]), "r"(a[2]), "r"(a[3]), "r"(b[0]), "r"(b[1]));
}
__device__ __forceinline__ float silu(float a) { return a / (1.f + __expf(-a)); }

#define STG_BYTES 32768
#define NSTG 3
#define SMEM_SZ (NSTG * STG_BYTES)   // 96 KB -> 2 CTAs/SM

// ---------------- pack unit: 8 fp32 -> 8 fp16 ---------------------------------
__device__ __forceinline__ void pack8(const float4* __restrict__ src,
                                      __half* __restrict__ dst, size_t u) {
    float4 v0 = src[u * 2], v1 = src[u * 2 + 1];
    uint4 o;
    o.x = f22h(v0.x, v0.y);
    o.y = f22h(v0.z, v0.w);
    o.z = f22h(v1.x, v1.y);
    o.w = f22h(v1.z, v1.w);
    ((uint4*)dst)[u] = o;
}

// tickets: [0,512) w13 (64/expert), [512,1536) x (8/128-row chunk), [1536,2048) w2
__device__ void exec_ticket(int tk, int tid,
                            const float4* __restrict__ x,  const float4* __restrict__ w1,
                            const float4* __restrict__ w3, const float4* __restrict__ w2) {
    if (tk < 512) {
        int e = tk >> 6, wi = tk & 63;
        size_t base = (size_t)wi * 8192;                 // unit within expert concat
        for (int k = 0; k < 64; ++k) {
            size_t u = base + tid + (size_t)k * 128;     // [0, 524288)
            if (u < 262144) pack8(w1, g_w1, (size_t)e * 262144 + u);
            else            pack8(w3, g_w3, (size_t)e * 262144 + (u - 262144));
        }
    } else if (tk < 1536) {
        size_t base = (size_t)(tk - 512) * 4096;
        for (int k = 0; k < 32; ++k) pack8(x, g_x, base + tid + (size_t)k * 128);
    } else {
        size_t base = (size_t)(tk - 1536) * 4096;
        for (int k = 0; k < 32; ++k) pack8(w2, g_w2, base + tid + (size_t)k * 128);
    }
}

__global__ void init_cnt() {
    int i = threadIdx.x;
    if (i == 0) { g_ticket = 0; g_w2cnt = 0; }
    if (i < 8) g_w13cnt[i] = 0;
    if (i < 128) { g_xcnt[i] = 0; g_hcnt[i] = 0; }
}

// ---------------- fused MoE kernel --------------------------------------------
// bids [0,2048): GEMM1 tiles; [2048,4096): GEMM2 tiles.
__global__ void __launch_bounds__(128, 2) moe_fused(
    const float4* __restrict__ xin, const float4* __restrict__ w1in,
    const float4* __restrict__ w3in, const float4* __restrict__ w2in,
    float* __restrict__ out) {
    extern __shared__ __half sm[];
    __shared__ int s_tk;
    const uint32_t sb = smem_u32(sm);
    const int tid = threadIdx.x, lane = tid & 31, wid = tid >> 5;
    const int g = lane >> 2, t = lane & 3, s7 = lane & 7;

    if (blockIdx.x < 2048) {
        // ======================= GEMM1 tile =======================
        const int bx = blockIdx.x;
        const int e = bx >> 8, mt = (bx >> 4) & 15, nt = bx & 15;
        const int mtg = bx >> 4;                       // 0..127
        const int m0 = e * 2048 + mt * 128, n0 = nt * 64;

        // cooperative wait: pull pack tickets until deps satisfied
        for (;;) {
            if (tid == 0) {
                int ok = (atomicAdd(&g_w13cnt[e], 0) >= 64) &&
                         (atomicAdd(&g_xcnt[mtg], 0) >= 8);
                s_tk = ok ? -1 : atomicAdd(&g_ticket, 1);
            }
            __syncthreads();
            int tk = s_tk;
            __syncthreads();
            if (tk < 0) break;
            if (tk < 2048) {
                exec_ticket(tk, tid, xin, w1in, w3in, w2in);
                __threadfence();
                __syncthreads();
                if (tid == 0) {
                    if (tk < 512)       atomicAdd(&g_w13cnt[tk >> 6], 1);
                    else if (tk < 1536) atomicAdd(&g_xcnt[(tk - 512) >> 3], 1);
                    else                atomicAdd(&g_w2cnt, 1);
                }
            } else if (tid == 0) __nanosleep(256);
        }

        const __half* A  = g_x  + (size_t)m0 * D_;
        const __half* B1 = g_w1 + (size_t)(e * H_ + n0) * D_;
        const __half* B3 = g_w3 + (size_t)(e * H_ + n0) * D_;
        const int KIT = D_ / 64;  // 32
        const int m_off = (wid & 1) * 64, n_off = (wid >> 1) * 32;

        uint32_t aA[4], bA[4];
        #pragma unroll
        for (int kk = 0; kk < 4; ++kk) {
            aA[kk] = sb + (uint32_t)(m_off + (lane & 15)) * 128u
                        + 16u * ((((lane >> 4) | (kk << 1)) ^ s7));
            bA[kk] = sb + 16384u + (uint32_t)(n_off + 8 * (lane >> 4) + s7) * 128u
                        + 16u * (((((lane >> 3) & 1) | (kk << 1)) ^ s7));
        }

        float c1[4][4][4], c3[4][4][4];
        #pragma unroll
        for (int i = 0; i < 4; ++i)
            #pragma unroll
            for (int j = 0; j < 4; ++j)
                #pragma unroll
                for (int q = 0; q < 4; ++q) { c1[i][j][q] = 0.f; c3[i][j][q] = 0.f; }

        auto issue = [&](int s, int kt) {
            __half* dst = sm + (size_t)s * (STG_BYTES / 2);
            const int koff = kt * 64;
            #pragma unroll
            for (int i = 0; i < 8; ++i) {
                int idx = tid + 128 * i, r = idx >> 3, c = idx & 7;
                cp16(dst + r * 64 + ((c ^ (r & 7)) << 3), A + (size_t)r * D_ + koff + c * 8);
            }
            __half* d1 = dst + 8192;
            __half* d3 = dst + 12288;
            #pragma unroll
            for (int i = 0; i < 4; ++i) {
                int idx = tid + 128 * i, r = idx >> 3, c = idx & 7;
                cp16(d1 + r * 64 + ((c ^ (r & 7)) << 3), B1 + (size_t)r * D_ + koff + c * 8);
                cp16(d3 + r * 64 + ((c ^ (r & 7)) << 3), B3 + (size_t)r * D_ + koff + c * 8);
            }
            asm volatile("cp.async.commit_group;" ::: "memory");
        };

        uint32_t a[2][4][4], b1f[2][4][2], b3f[2][4][2];
        auto ldfrag = [&](int kk, int pb, uint32_t soff) {
            #pragma unroll
            for (int mi = 0; mi < 4; ++mi)
                ldm_x4(a[pb][mi][0], a[pb][mi][1], a[pb][mi][2], a[pb][mi][3],
                       aA[kk] + soff + mi * 2048u);
            #pragma unroll
            for (int j = 0; j < 2; ++j) {
                ldm_x4(b1f[pb][2*j][0], b1f[pb][2*j][1], b1f[pb][2*j+1][0], b1f[pb][2*j+1][1],
                       bA[kk] + soff + j * 2048u);
                ldm_x4(b3f[pb][2*j][0], b3f[pb][2*j][1], b3f[pb][2*j+1][0], b3f[pb][2*j+1][1],
                       bA[kk] + soff + 8192u + j * 2048u);
            }
        };

        issue(0, 0); issue(1, 1);
        int cs = 0;
        for (int kt = 0; kt < KIT; ++kt) {
            if (kt + 1 < KIT) asm volatile("cp.async.wait_group 1;" ::: "memory");
            else              asm volatile("cp.async.wait_group 0;" ::: "memory");
            __syncthreads();
            if (kt + 2 < KIT) { int ns = cs + 2; if (ns >= 3) ns -= 3; issue(ns, kt + 2); }
            const uint32_t soff = (uint32_t)cs * STG_BYTES;
            ldfrag(0, 0, soff);
            #pragma unroll
            for (int kk = 0; kk < 4; ++kk) {
                const int cb = kk & 1;
                if (kk < 3) ldfrag(kk + 1, cb ^ 1, soff);
                #pragma unroll
                for (int mi = 0; mi < 4; ++mi)
                    #pragma unroll
                    for (int nj = 0; nj < 4; ++nj) {
                        mma_f16(c1[mi][nj], a[cb][mi], b1f[cb][nj]);
                        mma_f16(c3[mi][nj], a[cb][mi], b3f[cb][nj]);
                    }
            }
            if (++cs == 3) cs = 0;
        }

        // epilogue: h = fp16(silu(c1)*c3), then signal
        #pragma unroll
        for (int mi = 0; mi < 4; ++mi)
            #pragma unroll
            for (int nj = 0; nj < 4; ++nj) {
                int r0 = m0 + m_off + 16 * mi + g;
                int col = n0 + n_off + 8 * nj + 2 * t;
                uint32_t v0 = f22h(silu(c1[mi][nj][0]) * c3[mi][nj][0],
                                   silu(c1[mi][nj][1]) * c3[mi][nj][1]);
                uint32_t v1 = f22h(silu(c1[mi][nj][2]) * c3[mi][nj][2],
                                   silu(c1[mi][nj][3]) * c3[mi][nj][3]);
                *(uint32_t*)(g_h + (size_t)r0 * H_ + col)       = v0;
                *(uint32_t*)(g_h + (size_t)(r0 + 8) * H_ + col) = v1;
            }
        __threadfence();
        __syncthreads();
        if (tid == 0) atomicAdd(&g_hcnt[mtg], 1);

    } else {
        // ======================= GEMM2 tile =======================
        const int bx = blockIdx.x - 2048;
        const int e = bx >> 8, mt = (bx >> 4) & 15, nt = bx & 15;
        const int mtg = bx >> 4;
        const int m0 = e * 2048 + mt * 128, n0 = nt * 128;

        for (;;) {
            if (tid == 0) {
                int ok = (atomicAdd(&g_w2cnt, 0) >= 512) &&
                         (atomicAdd(&g_hcnt[mtg], 0) >= 16);
                s_tk = ok ? -1 : atomicAdd(&g_ticket, 1);
            }
            __syncthreads();
            int tk = s_tk;
            __syncthreads();
            if (tk < 0) break;
            if (tk < 2048) {
                exec_ticket(tk, tid, xin, w1in, w3in, w2in);
                __threadfence();
                __syncthreads();
                if (tid == 0) {
                    if (tk < 512)       atomicAdd(&g_w13cnt[tk >> 6], 1);
                    else if (tk < 1536) atomicAdd(&g_xcnt[(tk - 512) >> 3], 1);
                    else                atomicAdd(&g_w2cnt, 1);
                }
            } else if (tid == 0) __nanosleep(256);
        }

        const __half* A = g_h  + (size_t)m0 * H_;
        const __half* B = g_w2 + ((size_t)e * D_ + n0) * H_;
        const int KIT = H_ / 64;  // 16
        const int m_off = (wid & 1) * 64, n_off = (wid >> 1) * 64;

        uint32_t aA[4], bA[4];
        #pragma unroll
        for (int kk = 0; kk < 4; ++kk) {
            aA[kk] = sb + (uint32_t)(m_off + (lane & 15)) * 128u
                        + 16u * ((((lane >> 4) | (kk << 1)) ^ s7));
            bA[kk] = sb + 16384u + (uint32_t)(n_off + 8 * (lane >> 4) + s7) * 128u
                        + 16u * (((((lane >> 3) & 1) | (kk << 1)) ^ s7));
        }

        float cc[4][8][4];
        #pragma unroll
        for (int i = 0; i < 4; ++i)
            #pragma unroll
            for (int j = 0; j < 8; ++j)
                #pragma unroll
                for (int q = 0; q < 4; ++q) cc[i][j][q] = 0.f;

        auto issue = [&](int s, int kt) {
            __half* dst = sm + (size_t)s * (STG_BYTES / 2);
            const int koff = kt * 64;
            #pragma unroll
            for (int i = 0; i < 8; ++i) {
                int idx = tid + 128 * i, r = idx >> 3, c = idx & 7;
                cp16(dst + r * 64 + ((c ^ (r & 7)) << 3), A + (size_t)r * H_ + koff + c * 8);
            }
            __half* db = dst + 8192;
            #pragma unroll
            for (int i = 0; i < 8; ++i) {
                int idx = tid + 128 * i, r = idx >> 3, c = idx & 7;
                cp16(db + r * 64 + ((c ^ (r & 7)) << 3), B + (size_t)r * H_ + koff + c * 8);
            }
            asm volatile("cp.async.commit_group;" ::: "memory");
        };

        uint32_t a[2][4][4], bf[2][8][2];
        auto ldfrag = [&](int kk, int pb, uint32_t soff) {
            #pragma unroll
            for (int mi = 0; mi < 4; ++mi)
                ldm_x4(a[pb][mi][0], a[pb][mi][1], a[pb][mi][2], a[pb][mi][3],
                       aA[kk] + soff + mi * 2048u);
            #pragma unroll
            for (int j = 0; j < 4; ++j)
                ldm_x4(bf[pb][2*j][0], bf[pb][2*j][1], bf[pb][2*j+1][0], bf[pb][2*j+1][1],
                       bA[kk] + soff + j * 2048u);
        };

        issue(0, 0); issue(1, 1);
        int cs = 0;
        for (int kt = 0; kt < KIT; ++kt) {
            if (kt + 1 < KIT) asm volatile("cp.async.wait_group 1;" ::: "memory");
            else              asm volatile("cp.async.wait_group 0;" ::: "memory");
            __syncthreads();
            if (kt + 2 < KIT) { int ns = cs + 2; if (ns >= 3) ns -= 3; issue(ns, kt + 2); }
            const uint32_t soff = (uint32_t)cs * STG_BYTES;
            ldfrag(0, 0, soff);
            #pragma unroll
            for (int kk = 0; kk < 4; ++kk) {
                const int cb = kk & 1;
                if (kk < 3) ldfrag(kk + 1, cb ^ 1, soff);
                #pragma unroll
                for (int mi = 0; mi < 4; ++mi)
                    #pragma unroll
                    for (int nj = 0; nj < 8; ++nj)
                        mma_f16(cc[mi][nj], a[cb][mi], bf[cb][nj]);
            }
            if (++cs == 3) cs = 0;
        }

        #pragma unroll
        for (int mi = 0; mi < 4; ++mi)
            #pragma unroll
            for (int nj = 0; nj < 8; ++nj) {
                int r0 = m0 + m_off + 16 * mi + g;
                int col = n0 + n_off + 8 * nj + 2 * t;
                float2 v;
                v.x = cc[mi][nj][0]; v.y = cc[mi][nj][1];
                *(float2*)(out + (size_t)r0 * D_ + col) = v;
                v.x = cc[mi][nj][2]; v.y = cc[mi][nj][3];
                *(float2*)(out + (size_t)(r0 + 8) * D_ + col) = v;
            }
    }
}

// ---------------- launch ----------------
extern "C" void kernel_launch(void* const* d_in, const int* in_sizes, int n_in,
                              void* d_out, int out_size) {
    const float4* x  = (const float4*)d_in[0];
    const float4* w1 = (const float4*)d_in[2];
    const float4* w2 = (const float4*)d_in[3];
    const float4* w3 = (const float4*)d_in[4];
    float* out = (float*)d_out;

    init_cnt<<<1, 128>>>();

    cudaFuncSetAttribute(moe_fused, cudaFuncAttributeMaxDynamicSharedMemorySize, SMEM_SZ);
    moe_fused<<<4096, 128, SMEM_SZ>>>(x, w1, w3, w2, out);
}

// round 11
// speedup vs baseline: 1.2508x; 1.2508x over previous
#include <cuda_runtime.h>
#include <cuda_fp16.h>
#include <cstdint>

#define E_ 8
#define T_ 16384
#define D_ 2048
#define H_ 1024

// ---------------- scratch: fp16 operands, plain row-major ---------------------
__device__ __align__(1024) __half g_x [T_ * (size_t)D_];
__device__ __align__(1024) __half g_w1[E_ * (size_t)H_ * D_];
__device__ __align__(1024) __half g_w3[E_ * (size_t)H_ * D_];
__device__ __align__(1024) __half g_w2[E_ * (size_t)D_ * H_];
__device__ __align__(1024) __half g_h [T_ * (size_t)H_];

// ---------------- helpers ----------------
__device__ __forceinline__ uint32_t smem_u32(const void* p) {
    uint32_t a;
    asm("{ .reg .u64 t; cvta.to.shared.u64 t, %1; cvt.u32.u64 %0, t; }" : "=r"(a) : "l"(p));
    return a;
}
__device__ __forceinline__ uint32_t f22h(float lo, float hi) {   // fp16x2 {lo,hi}
    uint32_t r;
    asm("cvt.rn.f16x2.f32 %0, %1, %2;" : "=r"(r) : "f"(hi), "f"(lo));
    return r;
}
__device__ __forceinline__ void cp16(__half* sdst, const __half* gsrc) {
    uint32_t s = smem_u32(sdst);
    asm volatile("cp.async.cg.shared.global [%0], [%1], 16;" :: "r"(s), "l"(gsrc) : "memory");
}
__device__ __forceinline__ void ldm_x4(uint32_t& r0, uint32_t& r1, uint32_t& r2, uint32_t& r3,
                                       uint32_t addr) {
    asm volatile("ldmatrix.sync.aligned.m8n8.x4.shared.b16 {%0,%1,%2,%3}, [%4];"
                 : "=r"(r0), "=r"(r1), "=r"(r2), "=r"(r3) : "r"(addr));
}
__device__ __forceinline__ void mma_f16(float* c, const uint32_t* a, const uint32_t* b) {
    asm volatile(
        "mma.sync.aligned.m16n8k16.row.col.f32.f16.f16.f32 "
        "{%0,%1,%2,%3}, {%4,%5,%6,%7}, {%8,%9}, {%0,%1,%2,%3};"
        : "+f"(c[0]), "+f"(c[1]), "+f"(c[2]), "+f"(c[3])
        : "r"(a[0]), "r"(a[1]), "r"(a[2]), "r"(a[3]), "r"(b[0]), "r"(b[1]));
}
__device__ __forceinline__ float silu(float a) { return a / (1.f + __expf(-a)); }

#define STG_BYTES 32768
#define NSTG 3
#define SMEM_SZ (NSTG * STG_BYTES)   // 96 KB -> 2 CTAs/SM (192 KB)

// ---------------- pack x, w1, w3 (w2 packed inside moe_gemm1) -----------------
__global__ void pack_xw13(const float4* __restrict__ x, const float4* __restrict__ w1,
                          const float4* __restrict__ w3) {
    const size_t GX = (size_t)T_ * D_ / 8;
    const size_t GW = (size_t)E_ * H_ * D_ / 8;
    size_t id = (size_t)blockIdx.x * 256 + threadIdx.x;
    const float4* src; __half* dst; size_t gid;
    if (id < GX)               { src = x;  dst = g_x;  gid = id; }
    else if (id < GX + GW)     { src = w1; dst = g_w1; gid = id - GX; }
    else if (id < GX + 2 * GW) { src = w3; dst = g_w3; gid = id - GX - GW; }
    else return;
    float4 v0 = src[gid * 2], v1 = src[gid * 2 + 1];
    uint4 o;
    o.x = f22h(v0.x, v0.y);
    o.y = f22h(v0.z, v0.w);
    o.z = f22h(v1.x, v1.y);
    o.w = f22h(v1.z, v1.w);
    ((uint4*)dst)[gid] = o;
}

// ---------------- GEMM1 + fused w2 pack ---------------------------------------
// grid 2304: every 9th block packs w2 (256 blocks); 2048 GEMM tiles.
// GEMM: CTA 128M x 64N (each of w1,w3), BK=64; 256 thr, 8 warps (2m x 4n),
// warp 64x16 per weight. stage: A 16KB | B1 8KB | B3 8KB
__global__ void __launch_bounds__(256, 2) moe_gemm1(const float4* __restrict__ w2src) {
    extern __shared__ __half sm[];
    const uint32_t sb = smem_u32(sm);
    const int tid = threadIdx.x, lane = tid & 31, wid = tid >> 5;
    const int g = lane >> 2, t = lane & 3, s7 = lane & 7;
    const int bxr = blockIdx.x;

    if ((bxr % 9) == 8) {                          // ---- w2 pack branch ----
        const size_t N4 = (size_t)E_ * D_ * H_ / 8;   // 2097152 units of 8 floats
        size_t pid = (size_t)(bxr / 9);               // 0..255
        for (size_t i = pid * 256 + tid; i < N4; i += 256 * 256) {
            float4 v0 = w2src[i * 2], v1 = w2src[i * 2 + 1];
            uint4 o;
            o.x = f22h(v0.x, v0.y);
            o.y = f22h(v0.z, v0.w);
            o.z = f22h(v1.x, v1.y);
            o.w = f22h(v1.z, v1.w);
            ((uint4*)g_w2)[i] = o;
        }
        return;
    }
    const int bx = bxr - bxr / 9;                  // 0..2047 gemm tile index

    const int e = bx >> 8, mt = (bx >> 4) & 15, nt = bx & 15;
    const int m0 = e * 2048 + mt * 128, n0 = nt * 64;
    const __half* A  = g_x  + (size_t)m0 * D_;
    const __half* B1 = g_w1 + (size_t)(e * H_ + n0) * D_;
    const __half* B3 = g_w3 + (size_t)(e * H_ + n0) * D_;
    const int KIT = D_ / 64;  // 32
    const int m_off = (wid & 1) * 64, n_off = (wid >> 1) * 16;

    uint32_t aA[4], bA[4];
    #pragma unroll
    for (int kk = 0; kk < 4; ++kk) {
        aA[kk] = sb + (uint32_t)(m_off + (lane & 15)) * 128u
                    + 16u * ((((lane >> 4) | (kk << 1)) ^ s7));
        bA[kk] = sb + 16384u + (uint32_t)(n_off + 8 * (lane >> 4) + s7) * 128u
                    + 16u * (((((lane >> 3) & 1) | (kk << 1)) ^ s7));
    }

    float c1[4][2][4], c3[4][2][4];
    #pragma unroll
    for (int i = 0; i < 4; ++i)
        #pragma unroll
        for (int j = 0; j < 2; ++j)
            #pragma unroll
            for (int q = 0; q < 4; ++q) { c1[i][j][q] = 0.f; c3[i][j][q] = 0.f; }

    auto issue = [&](int s, int kt) {
        __half* dst = sm + (size_t)s * (STG_BYTES / 2);
        const int koff = kt * 64;
        #pragma unroll
        for (int i = 0; i < 4; ++i) {             // A: 128 rows x 8 chunks
            int idx = tid + 256 * i, r = idx >> 3, c = idx & 7;
            cp16(dst + r * 64 + ((c ^ (r & 7)) << 3), A + (size_t)r * D_ + koff + c * 8);
        }
        __half* d1 = dst + 8192;
        __half* d3 = dst + 12288;
        #pragma unroll
        for (int i = 0; i < 2; ++i) {             // B1,B3: 64 rows x 8 chunks
            int idx = tid + 256 * i, r = idx >> 3, c = idx & 7;
            cp16(d1 + r * 64 + ((c ^ (r & 7)) << 3), B1 + (size_t)r * D_ + koff + c * 8);
            cp16(d3 + r * 64 + ((c ^ (r & 7)) << 3), B3 + (size_t)r * D_ + koff + c * 8);
        }
        asm volatile("cp.async.commit_group;" ::: "memory");
    };

    issue(0, 0); issue(1, 1);
    int cs = 0;
    for (int kt = 0; kt < KIT; ++kt) {
        if (kt + 1 < KIT) asm volatile("cp.async.wait_group 1;" ::: "memory");
        else              asm volatile("cp.async.wait_group 0;" ::: "memory");
        __syncthreads();
        if (kt + 2 < KIT) { int ns = cs + 2; if (ns >= 3) ns -= 3; issue(ns, kt + 2); }
        const uint32_t soff = (uint32_t)cs * STG_BYTES;
        #pragma unroll
        for (int kk = 0; kk < 4; ++kk) {
            uint32_t a[4][4], b1f[2][2], b3f[2][2];
            #pragma unroll
            for (int mi = 0; mi < 4; ++mi)
                ldm_x4(a[mi][0], a[mi][1], a[mi][2], a[mi][3],
                       aA[kk] + soff + mi * 2048u);
            ldm_x4(b1f[0][0], b1f[0][1], b1f[1][0], b1f[1][1], bA[kk] + soff);
            ldm_x4(b3f[0][0], b3f[0][1], b3f[1][0], b3f[1][1], bA[kk] + soff + 8192u);
            #pragma unroll
            for (int mi = 0; mi < 4; ++mi)
                #pragma unroll
                for (int nj = 0; nj < 2; ++nj) {
                    mma_f16(c1[mi][nj], a[mi], b1f[nj]);
                    mma_f16(c3[mi][nj], a[mi], b3f[nj]);
                }
        }
        if (++cs == 3) cs = 0;
    }

    // epilogue: h = fp16(silu(c1)*c3), plain row-major
    #pragma unroll
    for (int mi = 0; mi < 4; ++mi)
        #pragma unroll
        for (int nj = 0; nj < 2; ++nj) {
            int r0 = m0 + m_off + 16 * mi + g;
            int col = n0 + n_off + 8 * nj + 2 * t;
            uint32_t v0 = f22h(silu(c1[mi][nj][0]) * c3[mi][nj][0],
                               silu(c1[mi][nj][1]) * c3[mi][nj][1]);
            uint32_t v1 = f22h(silu(c1[mi][nj][2]) * c3[mi][nj][2],
                               silu(c1[mi][nj][3]) * c3[mi][nj][3]);
            *(uint32_t*)(g_h + (size_t)r0 * H_ + col)       = v0;
            *(uint32_t*)(g_h + (size_t)(r0 + 8) * H_ + col) = v1;
        }
}

// ---------------- GEMM2: out = h @ w2^T ---------------------------------------
// CTA 128M x 128N, BK=64, K=1024; 256 thr, 8 warps (2m x 4n), warp 64x32
// grid 2048 = e(8) x mt(16) x nt(16); stage: A 16KB | B 16KB
__global__ void __launch_bounds__(256, 2) moe_gemm2(float* __restrict__ out) {
    extern __shared__ __half sm[];
    const uint32_t sb = smem_u32(sm);
    const int tid = threadIdx.x, lane = tid & 31, wid = tid >> 5;
    const int g = lane >> 2, t = lane & 3, s7 = lane & 7;
    const int bx = blockIdx.x;
    const int e = bx >> 8, mt = (bx >> 4) & 15, nt = bx & 15;
    const int m0 = e * 2048 + mt * 128, n0 = nt * 128;
    const __half* A = g_h  + (size_t)m0 * H_;
    const __half* B = g_w2 + ((size_t)e * D_ + n0) * H_;
    const int KIT = H_ / 64;  // 16
    const int m_off = (wid & 1) * 64, n_off = (wid >> 1) * 32;

    uint32_t aA[4], bA[4];
    #pragma unroll
    for (int kk = 0; kk < 4; ++kk) {
        aA[kk] = sb + (uint32_t)(m_off + (lane & 15)) * 128u
                    + 16u * ((((lane >> 4) | (kk << 1)) ^ s7));
        bA[kk] = sb + 16384u + (uint32_t)(n_off + 8 * (lane >> 4) + s7) * 128u
                    + 16u * (((((lane >> 3) & 1) | (kk << 1)) ^ s7));
    }

    float cc[4][4][4];
    #pragma unroll
    for (int i = 0; i < 4; ++i)
        #pragma unroll
        for (int j = 0; j < 4; ++j)
            #pragma unroll
            for (int q = 0; q < 4; ++q) cc[i][j][q] = 0.f;

    auto issue = [&](int s, int kt) {
        __half* dst = sm + (size_t)s * (STG_BYTES / 2);
        const int koff = kt * 64;
        #pragma unroll
        for (int i = 0; i < 4; ++i) {             // A: 128 x 8 chunks
            int idx = tid + 256 * i, r = idx >> 3, c = idx & 7;
            cp16(dst + r * 64 + ((c ^ (r & 7)) << 3), A + (size_t)r * H_ + koff + c * 8);
        }
        __half* db = dst + 8192;
        #pragma unroll
        for (int i = 0; i < 4; ++i) {             // B: 128 x 8 chunks
            int idx = tid + 256 * i, r = idx >> 3, c = idx & 7;
            cp16(db + r * 64 + ((c ^ (r & 7)) << 3), B + (size_t)r * H_ + koff + c * 8);
        }
        asm volatile("cp.async.commit_group;" ::: "memory");
    };

    issue(0, 0); issue(1, 1);
    int cs = 0;
    for (int kt = 0; kt < KIT; ++kt) {
        if (kt + 1 < KIT) asm volatile("cp.async.wait_group 1;" ::: "memory");
        else              asm volatile("cp.async.wait_group 0;" ::: "memory");
        __syncthreads();
        if (kt + 2 < KIT) { int ns = cs + 2; if (ns >= 3) ns -= 3; issue(ns, kt + 2); }
        const uint32_t soff = (uint32_t)cs * STG_BYTES;
        #pragma unroll
        for (int kk = 0; kk < 4; ++kk) {
            uint32_t a[4][4], bf[4][2];
            #pragma unroll
            for (int mi = 0; mi < 4; ++mi)
                ldm_x4(a[mi][0], a[mi][1], a[mi][2], a[mi][3],
                       aA[kk] + soff + mi * 2048u);
            #pragma unroll
            for (int j = 0; j < 2; ++j)
                ldm_x4(bf[2*j][0], bf[2*j][1], bf[2*j+1][0], bf[2*j+1][1],
                       bA[kk] + soff + j * 2048u);
            #pragma unroll
            for (int mi = 0; mi < 4; ++mi)
                #pragma unroll
                for (int nj = 0; nj < 4; ++nj)
                    mma_f16(cc[mi][nj], a[mi], bf[nj]);
        }
        if (++cs == 3) cs = 0;
    }

    #pragma unroll
    for (int mi = 0; mi < 4; ++mi)
        #pragma unroll
        for (int nj = 0; nj < 4; ++nj) {
            int r0 = m0 + m_off + 16 * mi + g;
            int col = n0 + n_off + 8 * nj + 2 * t;
            float2 v;
            v.x = cc[mi][nj][0]; v.y = cc[mi][nj][1];
            *(float2*)(out + (size_t)r0 * D_ + col) = v;
            v.x = cc[mi][nj][2]; v.y = cc[mi][nj][3];
            *(float2*)(out + (size_t)(r0 + 8) * D_ + col) = v;
        }
}

// ---------------- launch ----------------
extern "C" void kernel_launch(void* const* d_in, const int* in_sizes, int n_in,
                              void* d_out, int out_size) {
    const float4* x  = (const float4*)d_in[0];
    const float4* w1 = (const float4*)d_in[2];
    const float4* w2 = (const float4*)d_in[3];
    const float4* w3 = (const float4*)d_in[4];
    float* out = (float*)d_out;

    const size_t GX = (size_t)T_ * D_ / 8;
    const size_t GW = (size_t)E_ * H_ * D_ / 8;
    int nblk = (int)((GX + 2 * GW + 255) / 256);   // x, w1, w3 only

    pack_xw13<<<nblk, 256>>>(x, w1, w3);

    cudaFuncSetAttribute(moe_gemm1, cudaFuncAttributeMaxDynamicSharedMemorySize, SMEM_SZ);
    cudaFuncSetAttribute(moe_gemm2, cudaFuncAttributeMaxDynamicSharedMemorySize, SMEM_SZ);

    moe_gemm1<<<2304, 256, SMEM_SZ>>>(w2);   // 2048 gemm tiles + 256 w2-pack blocks
    moe_gemm2<<<2048, 256, SMEM_SZ>>>(out);
}